// round 11
// baseline (speedup 1.0000x reference)
#include <cuda_runtime.h>

// HungarianMatcher cost matrix: C[bs,nq,nt] =
//   5*L1(cxcywh) + 2*focal_class_cost(gathered by tgt_id) - 2*GIoU(xyxy)
//
// R10 = R9 + q-loop unroll x2 (ILP round done right):
//  - two query rows per iteration share the SAME per-thread target constants
//    (the register-expensive set), so ILP doubles (4 independent pair chains)
//    for only ~10 extra q-side registers — unlike R8's target-unroll which
//    blew up to 64 regs and regressed.
//  - __launch_bounds__(160, 8): reg cap 51, expected ~48-50 actual, 8 CTAs/SM.
//  - keeps R9's single-RCP giou and immediate-offset class gathers.

namespace {
constexpr int BS = 16, NQ = 900, NC = 91, NT = 1600;
constexpr int NROWS = BS * NQ;     // 14400
constexpr int TI = 20;             // query rows per block (even, 14400%20==0)
constexpr int TPB = 160;           // 5 warps
constexpr int TGT_PER_BLK = 2 * TPB;       // 320
constexpr int NTILE_T = NT / TGT_PER_BLK;  // 5
}

__device__ float  g_cls2[NROWS * NC];   // 2*cost_class + 2
__device__ float4 g_qxyxy[NROWS];
__device__ float4 g_txyxy[NT];
__device__ float  g_tarea[NT];
__device__ int    g_tid[NT];

// Fused prep: class table (+2 fold) + box xyxy + target area + id decode.
// tgt_ids is int64 in the reference; jax with x64 disabled materializes
// int32. Detect: for nonneg int64 < 2^31, every odd int32 word is 0.
// All detection reads stay within the int32 buffer size.
__global__ void prep_all(const float* __restrict__ logits,
                         const float* __restrict__ pred_boxes,
                         const float* __restrict__ tgt_boxes,
                         const int*   __restrict__ ids32) {
    int i = blockIdx.x * blockDim.x + threadIdx.x;
    if (i < NROWS * NC) {
        float x = logits[i];
        float p = __fdividef(1.0f, 1.0f + __expf(-x));
        float omp = 1.0f - p;
        float pos = 0.25f * omp * omp * (-__logf(p + 1e-8f));
        float neg = 0.75f * p * p * (-__logf(omp + 1e-8f));
        g_cls2[i] = 2.0f * (pos - neg) + 2.0f;   // +2 from -2*giou's (-1) term
    }
    if (i < NROWS + NT) {
        if (i < NROWS) {
            float4 b = reinterpret_cast<const float4*>(pred_boxes)[i];
            float4 xy;
            xy.x = b.x - 0.5f * b.z; xy.y = b.y - 0.5f * b.w;
            xy.z = b.x + 0.5f * b.z; xy.w = b.y + 0.5f * b.w;
            g_qxyxy[i] = xy;
        } else {
            int j = i - NROWS;
            float4 b = reinterpret_cast<const float4*>(tgt_boxes)[j];
            float4 xy;
            xy.x = b.x - 0.5f * b.z; xy.y = b.y - 0.5f * b.w;
            xy.z = b.x + 0.5f * b.z; xy.w = b.y + 0.5f * b.w;
            g_txyxy[j] = xy;
            g_tarea[j] = b.z * b.w;
        }
    }
    if (i < NT) {
        bool is64 = true;
#pragma unroll
        for (int k = 1; k < 128; k += 2)
            is64 &= (ids32[k] == 0);
        g_tid[i] = is64 ? ids32[2 * i] : ids32[i];
    }
}

__device__ __forceinline__ float pair_cost(
    const float4 qxy, const float4 qc, const float qarea,
    const float4 txy, const float4 tc, const float tarea,
    const float cls2p)
{
    // L1 on cxcywh
    float bb = fabsf(qc.x - tc.x) + fabsf(qc.y - tc.y)
             + fabsf(qc.z - tc.z) + fabsf(qc.w - tc.w);
    // enclosing box; intersection via identity:
    //   min(q2,t2) - max(q1,t1) = (qw + tw) - ex
    float ex = fmaxf(qxy.z, txy.z) - fminf(qxy.x, txy.x);
    float ey = fmaxf(qxy.w, txy.w) - fminf(qxy.y, txy.y);
    float w  = fmaxf((qc.z + tc.z) - ex, 0.0f);
    float h  = fmaxf((qc.w + tc.w) - ey, 0.0f);
    float inter = w * h;
    float uni = (qarea + tarea) - inter;
    float ae  = ex * ey;
    // inter/uni + uni/ae = (inter*ae + uni^2) / (uni*ae): single RCP per pair
    float num = fmaf(inter, ae, uni * uni);
    float r   = __fdividef(1.0f, uni * ae);
    float c   = fmaf(5.0f, bb, cls2p);
    return fmaf(-2.0f, num * r, c);
}

__global__ void __launch_bounds__(TPB, 8)
cost_kernel(const float* __restrict__ pred_boxes,
            const float* __restrict__ tgt_boxes,
            float* __restrict__ out)
{
    __shared__ float  s_cls[TI * NC];   // 7.3 KB
    __shared__ float4 s_qxy[TI];
    __shared__ float4 s_qc[TI];

    const int t  = threadIdx.x;
    const int r0 = blockIdx.x * TI;
    const int j0 = blockIdx.y * TGT_PER_BLK + 2 * t;

    for (int k = t; k < TI * NC; k += TPB)
        s_cls[k] = g_cls2[r0 * NC + k];
    if (t < TI) {
        s_qxy[t] = g_qxyxy[r0 + t];
        s_qc[t]  = reinterpret_cast<const float4*>(pred_boxes)[r0 + t];
    }

    // per-thread target constants (registers; must stay resident — see R5)
    const float4 t0xy = g_txyxy[j0];
    const float4 t1xy = g_txyxy[j0 + 1];
    const float  t0a  = g_tarea[j0];
    const float  t1a  = g_tarea[j0 + 1];
    const float4 t0c  = reinterpret_cast<const float4*>(tgt_boxes)[j0];
    const float4 t1c  = reinterpret_cast<const float4*>(tgt_boxes)[j0 + 1];
    const int id0 = g_tid[j0];
    const int id1 = g_tid[j0 + 1];
    __syncthreads();

    // hoisted gather bases: per-q access is [imm] off these
    const float* p0 = s_cls + id0;
    const float* p1 = s_cls + id1;

    float* orow = out + (size_t)r0 * NT + j0;

#pragma unroll
    for (int q = 0; q < TI; q += 2) {
        // q-row A
        const float4 qxyA = s_qxy[q];
        const float4 qcA  = s_qc[q];
        const float  qaA  = qcA.z * qcA.w;
        // q-row B (independent chain sharing target registers)
        const float4 qxyB = s_qxy[q + 1];
        const float4 qcB  = s_qc[q + 1];
        const float  qaB  = qcB.z * qcB.w;

        float a0 = pair_cost(qxyA, qcA, qaA, t0xy, t0c, t0a, p0[q * NC]);
        float b0 = pair_cost(qxyB, qcB, qaB, t0xy, t0c, t0a, p0[(q + 1) * NC]);
        float a1 = pair_cost(qxyA, qcA, qaA, t1xy, t1c, t1a, p1[q * NC]);
        float b1 = pair_cost(qxyB, qcB, qaB, t1xy, t1c, t1a, p1[(q + 1) * NC]);

        *reinterpret_cast<float2*>(orow + (size_t)q * NT)       = make_float2(a0, a1);
        *reinterpret_cast<float2*>(orow + (size_t)(q + 1) * NT) = make_float2(b0, b1);
    }
}

extern "C" void kernel_launch(void* const* d_in, const int* in_sizes, int n_in,
                              void* d_out, int out_size) {
    const float* logits = (const float*)d_in[0];   // [16,900,91]
    const float* pboxes = (const float*)d_in[1];   // [16,900,4]
    const float* tboxes = (const float*)d_in[2];   // [1600,4]
    const int*   ids    = (const int*)d_in[3];     // [1600] (int32 or int64 view)
    float* out = (float*)d_out;                    // [16,900,1600]

    prep_all<<<(NROWS * NC + 255) / 256, 256>>>(logits, pboxes, tboxes, ids);
    dim3 grid(NROWS / TI, NTILE_T);
    cost_kernel<<<grid, TPB>>>(pboxes, tboxes, out);
}

// round 12
// speedup vs baseline: 1.1016x; 1.1016x over previous
#include <cuda_runtime.h>

// HungarianMatcher cost matrix: C[bs,nq,nt] =
//   5*L1(cxcywh) + 2*focal_class_cost(gathered by tgt_id) - 2*GIoU(xyxy)
//
// R11 = R9 (best-known: 2 tgt/thread, TPB=160, minblocks 9, single-RCP giou)
// plus three independent small fixes:
//  - TI 20 -> 18: 4000 blocks = exactly 3 waves at 9 CTAs/SM (was 2.7 waves,
//    i.e. a 70%-full tail wave).
//  - class tile transposed in smem: s_clsT[91][22]; the two class values for
//    (q, q+1) come from ONE aligned LDS.64 per target (half the gather
//    instructions + MIO requests; stride 22 keeps ~2-way conflicts, same as
//    the old layout).
//  - q-unroll from R10 reverted (proven neutral on kernel, worse on total).

namespace {
constexpr int BS = 16, NQ = 900, NC = 91, NT = 1600;
constexpr int NROWS = BS * NQ;     // 14400
constexpr int TI = 18;             // query rows per block (14400 % 18 == 0)
constexpr int TI_PAD = 22;         // even (LDS.64 alignment), gcd(22,32)=2
constexpr int TPB = 160;           // 5 warps
constexpr int TGT_PER_BLK = 2 * TPB;       // 320
constexpr int NTILE_T = NT / TGT_PER_BLK;  // 5
}

__device__ float  g_cls2[NROWS * NC];   // 2*cost_class + 2 (row-major)
__device__ float4 g_qxyxy[NROWS];
__device__ float4 g_txyxy[NT];
__device__ float  g_tarea[NT];
__device__ int    g_tid[NT];

// Fused prep: class table (+2 fold) + box xyxy + target area + id decode.
// tgt_ids is int64 in the reference; jax with x64 disabled materializes
// int32. Detect: for nonneg int64 < 2^31, every odd int32 word is 0.
// All detection reads stay within the int32 buffer size.
__global__ void prep_all(const float* __restrict__ logits,
                         const float* __restrict__ pred_boxes,
                         const float* __restrict__ tgt_boxes,
                         const int*   __restrict__ ids32) {
    int i = blockIdx.x * blockDim.x + threadIdx.x;
    if (i < NROWS * NC) {
        float x = logits[i];
        float p = __fdividef(1.0f, 1.0f + __expf(-x));
        float omp = 1.0f - p;
        float pos = 0.25f * omp * omp * (-__logf(p + 1e-8f));
        float neg = 0.75f * p * p * (-__logf(omp + 1e-8f));
        g_cls2[i] = 2.0f * (pos - neg) + 2.0f;   // +2 from -2*giou's (-1) term
    }
    if (i < NROWS + NT) {
        if (i < NROWS) {
            float4 b = reinterpret_cast<const float4*>(pred_boxes)[i];
            float4 xy;
            xy.x = b.x - 0.5f * b.z; xy.y = b.y - 0.5f * b.w;
            xy.z = b.x + 0.5f * b.z; xy.w = b.y + 0.5f * b.w;
            g_qxyxy[i] = xy;
        } else {
            int j = i - NROWS;
            float4 b = reinterpret_cast<const float4*>(tgt_boxes)[j];
            float4 xy;
            xy.x = b.x - 0.5f * b.z; xy.y = b.y - 0.5f * b.w;
            xy.z = b.x + 0.5f * b.z; xy.w = b.y + 0.5f * b.w;
            g_txyxy[j] = xy;
            g_tarea[j] = b.z * b.w;
        }
    }
    if (i < NT) {
        bool is64 = true;
#pragma unroll
        for (int k = 1; k < 128; k += 2)
            is64 &= (ids32[k] == 0);
        g_tid[i] = is64 ? ids32[2 * i] : ids32[i];
    }
}

__device__ __forceinline__ float pair_cost(
    const float4 qxy, const float4 qc, const float qarea,
    const float4 txy, const float4 tc, const float tarea,
    const float cls2p)
{
    // L1 on cxcywh
    float bb = fabsf(qc.x - tc.x) + fabsf(qc.y - tc.y)
             + fabsf(qc.z - tc.z) + fabsf(qc.w - tc.w);
    // enclosing box; intersection via identity:
    //   min(q2,t2) - max(q1,t1) = (qw + tw) - ex
    float ex = fmaxf(qxy.z, txy.z) - fminf(qxy.x, txy.x);
    float ey = fmaxf(qxy.w, txy.w) - fminf(qxy.y, txy.y);
    float w  = fmaxf((qc.z + tc.z) - ex, 0.0f);
    float h  = fmaxf((qc.w + tc.w) - ey, 0.0f);
    float inter = w * h;
    float uni = (qarea + tarea) - inter;
    float ae  = ex * ey;
    // inter/uni + uni/ae = (inter*ae + uni^2) / (uni*ae): single RCP per pair
    float num = fmaf(inter, ae, uni * uni);
    float r   = __fdividef(1.0f, uni * ae);
    float c   = fmaf(5.0f, bb, cls2p);
    return fmaf(-2.0f, num * r, c);
}

__global__ void __launch_bounds__(TPB, 9)
cost_kernel(const float* __restrict__ pred_boxes,
            const float* __restrict__ tgt_boxes,
            float* __restrict__ out)
{
    __shared__ float  s_clsT[NC * TI_PAD];  // transposed: [class][q], 8.0 KB
    __shared__ float4 s_qxy[TI];
    __shared__ float4 s_qc[TI];

    const int t  = threadIdx.x;
    const int r0 = blockIdx.x * TI;
    const int j0 = blockIdx.y * TGT_PER_BLK + 2 * t;

    // Stage class tile transposed. Threads t<91 each own class column c=t;
    // reads are coalesced across t (consecutive addresses within each q row),
    // STS stride TI_PAD=22 across lanes is conflict-free.
    if (t < NC) {
#pragma unroll
        for (int q = 0; q < TI; ++q)
            s_clsT[t * TI_PAD + q] = g_cls2[(r0 + q) * NC + t];
    } else if (t < NC + TI) {
        int qq = t - NC;
        s_qxy[qq] = g_qxyxy[r0 + qq];
        s_qc[qq]  = reinterpret_cast<const float4*>(pred_boxes)[r0 + qq];
    }

    // per-thread target constants (registers; must stay resident — see R5)
    const float4 t0xy = g_txyxy[j0];
    const float4 t1xy = g_txyxy[j0 + 1];
    const float  t0a  = g_tarea[j0];
    const float  t1a  = g_tarea[j0 + 1];
    const float4 t0c  = reinterpret_cast<const float4*>(tgt_boxes)[j0];
    const float4 t1c  = reinterpret_cast<const float4*>(tgt_boxes)[j0 + 1];
    const int id0 = g_tid[j0];
    const int id1 = g_tid[j0 + 1];
    __syncthreads();

    // gather bases: one LDS.64 per target fetches cls for (q, q+1)
    const float* pc0 = s_clsT + id0 * TI_PAD;
    const float* pc1 = s_clsT + id1 * TI_PAD;

    float* orow = out + (size_t)r0 * NT + j0;

#pragma unroll
    for (int q = 0; q < TI; q += 2) {
        const float2 cls0 = *reinterpret_cast<const float2*>(pc0 + q);
        const float2 cls1 = *reinterpret_cast<const float2*>(pc1 + q);

        {   // q-row q
            const float4 qxy = s_qxy[q];
            const float4 qc  = s_qc[q];
            const float  qa  = qc.z * qc.w;
            float c0 = pair_cost(qxy, qc, qa, t0xy, t0c, t0a, cls0.x);
            float c1 = pair_cost(qxy, qc, qa, t1xy, t1c, t1a, cls1.x);
            *reinterpret_cast<float2*>(orow + (size_t)q * NT) = make_float2(c0, c1);
        }
        {   // q-row q+1
            const float4 qxy = s_qxy[q + 1];
            const float4 qc  = s_qc[q + 1];
            const float  qa  = qc.z * qc.w;
            float c0 = pair_cost(qxy, qc, qa, t0xy, t0c, t0a, cls0.y);
            float c1 = pair_cost(qxy, qc, qa, t1xy, t1c, t1a, cls1.y);
            *reinterpret_cast<float2*>(orow + (size_t)(q + 1) * NT) = make_float2(c0, c1);
        }
    }
}

extern "C" void kernel_launch(void* const* d_in, const int* in_sizes, int n_in,
                              void* d_out, int out_size) {
    const float* logits = (const float*)d_in[0];   // [16,900,91]
    const float* pboxes = (const float*)d_in[1];   // [16,900,4]
    const float* tboxes = (const float*)d_in[2];   // [1600,4]
    const int*   ids    = (const int*)d_in[3];     // [1600] (int32 or int64 view)
    float* out = (float*)d_out;                    // [16,900,1600]

    prep_all<<<(NROWS * NC + 255) / 256, 256>>>(logits, pboxes, tboxes, ids);
    dim3 grid(NROWS / TI, NTILE_T);
    cost_kernel<<<grid, TPB>>>(pboxes, tboxes, out);
}